// round 15
// baseline (speedup 1.0000x reference)
#include <cuda_runtime.h>
#include <cstdint>

#define NBH 64
#define L   512
#define DD  64
#define SQP 68    // sQ row pad (floats)
#define SKP 260   // sKT / sP row pad (floats)

typedef unsigned long long ull;

// Scratch (device globals; no allocation in kernel_launch)
__device__ float g_ksumT[NBH * DD * L];   // [bh][d][j]  (transposed)
__device__ float g_vsum [NBH * L * DD];   // [bh][j][d]  (natural)

__device__ __forceinline__ ull pack2(float x) {
    ull r; unsigned int xi = __float_as_uint(x);
    asm("mov.b64 %0, {%1, %1};" : "=l"(r) : "r"(xi));
    return r;
}
__device__ __forceinline__ ull pack2f(float x, float y) {
    ull r;
    asm("mov.b64 %0, {%1, %2};" : "=l"(r) : "f"(x), "f"(y));
    return r;
}
__device__ __forceinline__ void ffma2(ull& c, ull a, ull b) {
    asm("fma.rn.f32x2 %0, %1, %2, %0;" : "+l"(c) : "l"(a), "l"(b));
}
__device__ __forceinline__ float2 unpack2(ull x) {
    float2 f;
    asm("mov.b64 {%0, %1}, %2;" : "=f"(f.x), "=f"(f.y) : "l"(x));
    return f;
}

// ---------------------------------------------------------------------------
// K1: reduce r; ksum TRANSPOSED [bh][d][j] via smem transpose, vsum natural.
// ---------------------------------------------------------------------------
__global__ __launch_bounds__(256)
void reduce_kv_kernel(const float* __restrict__ k, const float* __restrict__ v) {
    __shared__ float sT[DD * 65];
    const int t  = threadIdx.x;
    const int jb = blockIdx.x;
    const int bh = blockIdx.y;

    #pragma unroll
    for (int p = 0; p < 4; ++p) {
        int f4 = p * 256 + t;
        int jl = f4 >> 4, dq = (f4 & 15) << 2;
        size_t base = (((size_t)bh * L + jb * 64 + jl) * 4) * DD + dq;
        float4 a0 = *(const float4*)(k + base);
        float4 a1 = *(const float4*)(k + base + DD);
        float4 a2 = *(const float4*)(k + base + 2 * DD);
        float4 a3 = *(const float4*)(k + base + 3 * DD);
        sT[(dq + 0) * 65 + jl] = (a0.x + a1.x) + (a2.x + a3.x);
        sT[(dq + 1) * 65 + jl] = (a0.y + a1.y) + (a2.y + a3.y);
        sT[(dq + 2) * 65 + jl] = (a0.z + a1.z) + (a2.z + a3.z);
        sT[(dq + 3) * 65 + jl] = (a0.w + a1.w) + (a2.w + a3.w);
        float4 b0 = *(const float4*)(v + base);
        float4 b1 = *(const float4*)(v + base + DD);
        float4 b2 = *(const float4*)(v + base + 2 * DD);
        float4 b3 = *(const float4*)(v + base + 3 * DD);
        float4 vs;
        vs.x = (b0.x + b1.x) + (b2.x + b3.x);
        vs.y = (b0.y + b1.y) + (b2.y + b3.y);
        vs.z = (b0.z + b1.z) + (b2.z + b3.z);
        vs.w = (b0.w + b1.w) + (b2.w + b3.w);
        *(float4*)(g_vsum + ((size_t)bh * L + jb * 64 + jl) * DD + dq) = vs;
    }
    __syncthreads();
    #pragma unroll
    for (int p = 0; p < 4; ++p) {
        int f4 = p * 256 + t;
        int dl = f4 >> 4, jq = (f4 & 15) << 2;
        float4 o;
        o.x = sT[dl * 65 + jq + 0];
        o.y = sT[dl * 65 + jq + 1];
        o.z = sT[dl * 65 + jq + 2];
        o.w = sT[dl * 65 + jq + 3];
        *(float4*)(g_ksumT + ((size_t)bh * DD + dl) * L + jb * 64 + jq) = o;
    }
}

// ---------------------------------------------------------------------------
// K2 (fused): per CTA 64 q rows of one bh.
//   QK c=0: e=exp(s) -> raw to attn, lane-partial Z
//   QK c=1: e kept in regs, partial Z; Z shuffle-reduce
//   ONE syncthreads (sKT -> sP alias). Then all warp-local:
//     sP := chunk1 P (regs * iz) -> attn + sP ; PV over j=256..511 (V via LDG/L2)
//     sP := chunk0 P (attn re-read * iz) -> attn + sP ; PV over j=0..255
//   write O.
// smem: sQ[64][68] | sKT[64][260] (aliased by sP) = 84KB -> 2 CTA/SM.
// ---------------------------------------------------------------------------
extern __shared__ float smem[];

__global__ __launch_bounds__(256, 2)
void attn_fused(const float* __restrict__ q,
                const float* __restrict__ omega,
                const int*   __restrict__ mask,
                float* __restrict__ attn,
                float* __restrict__ out_o) {
    float* sQ  = smem;              // [64][SQP]
    float* sKT = smem + 64 * SQP;   // [64][SKP]
    float* sP  = sKT;               // alias (sKT dead after QK)

    const int t  = threadIdx.x;
    const int bh = blockIdx.y;
    const int b  = bh >> 3;
    const int qb = blockIdx.x * 64;
    const int w  = t >> 5, l = t & 31;

    // fill sQ (fold 1/8)
    #pragma unroll
    for (int p = 0; p < 4; ++p) {
        int f4 = p * 256 + t;
        int r = f4 >> 4, dq = (f4 & 15) << 2;
        float4 qv = *(const float4*)(q + ((size_t)bh * L + qb + r) * DD + dq);
        qv.x *= 0.125f; qv.y *= 0.125f; qv.z *= 0.125f; qv.w *= 0.125f;
        *(float4*)(sQ + r * SQP + dq) = qv;
    }

    float Zp[8], Zinv[8];
    #pragma unroll
    for (int r = 0; r < 8; ++r) Zp[r] = 0.f;

    ull acc[8][4];

    #pragma unroll
    for (int c = 0; c < 2; ++c) {
        __syncthreads();
        // fill sKT chunk c
        #pragma unroll
        for (int p = 0; p < 16; ++p) {
            int f4 = p * 256 + t;
            int d = f4 >> 6, cq = (f4 & 63) << 2;
            *(float4*)(sKT + d * SKP + cq) =
                *(const float4*)(g_ksumT + ((size_t)bh * DD + d) * L + c * 256 + cq);
        }
        __syncthreads();

        #pragma unroll
        for (int r = 0; r < 8; ++r)
            #pragma unroll
            for (int i = 0; i < 4; ++i) acc[r][i] = 0;

        const float* bp = sKT + 4 * l;
        #pragma unroll 2
        for (int d = 0; d < DD; d += 4) {
            float4 a[8];
            #pragma unroll
            for (int r = 0; r < 8; ++r)
                a[r] = *(const float4*)(sQ + (8 * w + r) * SQP + d);
            #pragma unroll
            for (int dd = 0; dd < 4; ++dd) {
                ulonglong2 b0 = *(const ulonglong2*)(bp + (d + dd) * SKP);
                ulonglong2 b1 = *(const ulonglong2*)(bp + (d + dd) * SKP + 128);
                #pragma unroll
                for (int r = 0; r < 8; ++r) {
                    float av = (dd == 0) ? a[r].x : (dd == 1) ? a[r].y
                             : (dd == 2) ? a[r].z : a[r].w;
                    ull ar = pack2(av);
                    ffma2(acc[r][0], ar, b0.x);
                    ffma2(acc[r][1], ar, b0.y);
                    ffma2(acc[r][2], ar, b1.x);
                    ffma2(acc[r][3], ar, b1.y);
                }
            }
        }

        // epilogue: e = mask ? 0 : exp(u*omega); lane-partial Z
        #pragma unroll
        for (int r = 0; r < 8; ++r) {
            int gi = qb + 8 * w + r;
            size_t orow = ((size_t)b * L + gi) * L + c * 256;
            float4 o0 = *(const float4*)(omega + orow + 4 * l);
            float4 o1 = *(const float4*)(omega + orow + 128 + 4 * l);
            int4 m0 = *(const int4*)(mask + orow + 4 * l);
            int4 m1 = *(const int4*)(mask + orow + 128 + 4 * l);
            float2 u0 = unpack2(acc[r][0]), u1 = unpack2(acc[r][1]);
            float2 u2 = unpack2(acc[r][2]), u3 = unpack2(acc[r][3]);
            float e0 = m0.x ? 0.f : __expf(u0.x * o0.x);
            float e1 = m0.y ? 0.f : __expf(u0.y * o0.y);
            float e2 = m0.z ? 0.f : __expf(u1.x * o0.z);
            float e3 = m0.w ? 0.f : __expf(u1.y * o0.w);
            float e4 = m1.x ? 0.f : __expf(u2.x * o1.x);
            float e5 = m1.y ? 0.f : __expf(u2.y * o1.y);
            float e6 = m1.z ? 0.f : __expf(u3.x * o1.z);
            float e7 = m1.w ? 0.f : __expf(u3.y * o1.w);
            Zp[r] += ((e0 + e1) + (e2 + e3)) + ((e4 + e5) + (e6 + e7));
            if (c == 0) {
                size_t arow = ((size_t)bh * L + gi) * L;
                *(float4*)(attn + arow + 4 * l)       = make_float4(e0, e1, e2, e3);
                *(float4*)(attn + arow + 128 + 4 * l) = make_float4(e4, e5, e6, e7);
            } else {
                acc[r][0] = pack2f(e0, e1);
                acc[r][1] = pack2f(e2, e3);
                acc[r][2] = pack2f(e4, e5);
                acc[r][3] = pack2f(e6, e7);
            }
        }
    }

    // Z reduction across lanes (covers both chunks)
    #pragma unroll
    for (int r = 0; r < 8; ++r) {
        float z = Zp[r];
        #pragma unroll
        for (int o = 16; o > 0; o >>= 1)
            z += __shfl_xor_sync(0xffffffffu, z, o);
        Zinv[r] = 1.0f / z;
    }

    __syncthreads();   // ALL warps done reading sKT before sP overwrites it

    const float* vbase = g_vsum + (size_t)bh * L * DD;
    ull oacc[8];
    #pragma unroll
    for (int r = 0; r < 8; ++r) oacc[r] = 0;

    // ---- chunk 1: write normalized P (regs) to attn + sP, then PV j=256..511
    #pragma unroll
    for (int r = 0; r < 8; ++r) {
        int gi = qb + 8 * w + r;
        float iz = Zinv[r];
        float2 e0 = unpack2(acc[r][0]), e1 = unpack2(acc[r][1]);
        float2 e2 = unpack2(acc[r][2]), e3 = unpack2(acc[r][3]);
        float4 p0 = make_float4(e0.x * iz, e0.y * iz, e1.x * iz, e1.y * iz);
        float4 p1 = make_float4(e2.x * iz, e2.y * iz, e3.x * iz, e3.y * iz);
        size_t arow = ((size_t)bh * L + gi) * L + 256;
        *(float4*)(attn + arow + 4 * l)       = p0;
        *(float4*)(attn + arow + 128 + 4 * l) = p1;
        *(float4*)(sP + (8 * w + r) * SKP + 4 * l)       = p0;
        *(float4*)(sP + (8 * w + r) * SKP + 128 + 4 * l) = p1;
    }
    __syncwarp();

    #pragma unroll 4
    for (int j = 0; j < 256; j += 4) {
        ull v0 = *(const ull*)(vbase + (size_t)(256 + j + 0) * DD + 2 * l);
        ull v1 = *(const ull*)(vbase + (size_t)(256 + j + 1) * DD + 2 * l);
        ull v2 = *(const ull*)(vbase + (size_t)(256 + j + 2) * DD + 2 * l);
        ull v3 = *(const ull*)(vbase + (size_t)(256 + j + 3) * DD + 2 * l);
        float4 a4[8];
        #pragma unroll
        for (int r = 0; r < 8; ++r)
            a4[r] = *(const float4*)(sP + (8 * w + r) * SKP + j);
        #pragma unroll
        for (int r = 0; r < 8; ++r) ffma2(oacc[r], pack2(a4[r].x), v0);
        #pragma unroll
        for (int r = 0; r < 8; ++r) ffma2(oacc[r], pack2(a4[r].y), v1);
        #pragma unroll
        for (int r = 0; r < 8; ++r) ffma2(oacc[r], pack2(a4[r].z), v2);
        #pragma unroll
        for (int r = 0; r < 8; ++r) ffma2(oacc[r], pack2(a4[r].w), v3);
    }
    __syncwarp();

    // ---- chunk 0: fixup (attn raw re-read, L2-hot) -> attn + sP, PV j=0..255
    #pragma unroll
    for (int r = 0; r < 8; ++r) {
        int gi = qb + 8 * w + r;
        size_t arow = ((size_t)bh * L + gi) * L;
        float4 x0 = *(const float4*)(attn + arow + 4 * l);
        float4 x1 = *(const float4*)(attn + arow + 128 + 4 * l);
        float iz = Zinv[r];
        x0.x *= iz; x0.y *= iz; x0.z *= iz; x0.w *= iz;
        x1.x *= iz; x1.y *= iz; x1.z *= iz; x1.w *= iz;
        *(float4*)(attn + arow + 4 * l)       = x0;
        *(float4*)(attn + arow + 128 + 4 * l) = x1;
        *(float4*)(sP + (8 * w + r) * SKP + 4 * l)       = x0;
        *(float4*)(sP + (8 * w + r) * SKP + 128 + 4 * l) = x1;
    }
    __syncwarp();

    #pragma unroll 4
    for (int j = 0; j < 256; j += 4) {
        ull v0 = *(const ull*)(vbase + (size_t)(j + 0) * DD + 2 * l);
        ull v1 = *(const ull*)(vbase + (size_t)(j + 1) * DD + 2 * l);
        ull v2 = *(const ull*)(vbase + (size_t)(j + 2) * DD + 2 * l);
        ull v3 = *(const ull*)(vbase + (size_t)(j + 3) * DD + 2 * l);
        float4 a4[8];
        #pragma unroll
        for (int r = 0; r < 8; ++r)
            a4[r] = *(const float4*)(sP + (8 * w + r) * SKP + j);
        #pragma unroll
        for (int r = 0; r < 8; ++r) ffma2(oacc[r], pack2(a4[r].x), v0);
        #pragma unroll
        for (int r = 0; r < 8; ++r) ffma2(oacc[r], pack2(a4[r].y), v1);
        #pragma unroll
        for (int r = 0; r < 8; ++r) ffma2(oacc[r], pack2(a4[r].z), v2);
        #pragma unroll
        for (int r = 0; r < 8; ++r) ffma2(oacc[r], pack2(a4[r].w), v3);
    }

    // write O: warp rows 8w..8w+7, lane d = 2l..2l+1
    #pragma unroll
    for (int r = 0; r < 8; ++r) {
        float2 ov = unpack2(oacc[r]);
        *(float2*)(out_o + ((size_t)bh * L + qb + 8 * w + r) * DD + 2 * l) = ov;
    }
}

// ---------------------------------------------------------------------------
extern "C" void kernel_launch(void* const* d_in, const int* in_sizes, int n_in,
                              void* d_out, int out_size) {
    const float* q     = (const float*)d_in[0];
    const float* k     = (const float*)d_in[1];
    const float* v     = (const float*)d_in[2];
    const float* omega = (const float*)d_in[3];
    const int*   mask  = (const int*)d_in[4];

    float* out_o    = (float*)d_out;
    float* out_attn = out_o + (size_t)NBH * L * DD;   // [output | attn]

    const int smem2 = (64 * SQP + 64 * SKP) * (int)sizeof(float);  // 83968
    cudaFuncSetAttribute(attn_fused, cudaFuncAttributeMaxDynamicSharedMemorySize, smem2);

    reduce_kv_kernel<<<dim3(8, NBH), 256>>>(k, v);
    attn_fused<<<dim3(8, NBH), 256, smem2>>>(q, omega, mask, out_attn, out_o);
}